// round 16
// baseline (speedup 1.0000x reference)
#include <cuda_runtime.h>
#include <cuda_fp16.h>
#include <cuda_bf16.h>

#define B_  8
#define Q_  256
#define K_  1024
#define D_  256
#define H_  128
#define DV_ 128

#define RPAD 132

__device__ __half2 g_q2[B_ * Q_ * H_];
__device__ __half2 g_k2[B_ * 8 * 64 * H_];
__device__ float   g_sc[B_ * Q_ * K_];

__device__ __forceinline__ __half2 tanh_h2(__half2 x) {
    __half2 y;
    asm("tanh.approx.f16x2 %0, %1;"
        : "=r"(*(unsigned int*)&y) : "r"(*(unsigned int*)&x));
    return y;
}

__device__ __forceinline__ unsigned int smem_u32(const void* p) {
    return (unsigned int)__cvta_generic_to_shared(p);
}

__device__ __forceinline__ void ldsm_x4(unsigned int& r0, unsigned int& r1,
                                        unsigned int& r2, unsigned int& r3,
                                        unsigned int a) {
    asm volatile("ldmatrix.sync.aligned.m8n8.x4.shared.b16 {%0,%1,%2,%3}, [%4];"
                 : "=r"(r0), "=r"(r1), "=r"(r2), "=r"(r3) : "r"(a));
}

__device__ __forceinline__ void ldsm_x4t(unsigned int& r0, unsigned int& r1,
                                         unsigned int& r2, unsigned int& r3,
                                         unsigned int a) {
    asm volatile("ldmatrix.sync.aligned.m8n8.x4.trans.shared.b16 {%0,%1,%2,%3}, [%4];"
                 : "=r"(r0), "=r"(r1), "=r"(r2), "=r"(r3) : "r"(a));
}

__device__ __forceinline__ void mma16816(float* c,
                                         unsigned int a0, unsigned int a1,
                                         unsigned int a2, unsigned int a3,
                                         unsigned int b0, unsigned int b1) {
    asm volatile("mma.sync.aligned.m16n8k16.row.col.f32.f16.f16.f32 "
                 "{%0,%1,%2,%3}, {%4,%5,%6,%7}, {%8,%9}, {%0,%1,%2,%3};"
                 : "+f"(c[0]), "+f"(c[1]), "+f"(c[2]), "+f"(c[3])
                 : "r"(a0), "r"(a1), "r"(a2), "r"(a3), "r"(b0), "r"(b1));
}

// ---------------------------------------------------------------------------
// Kernel 1: tensor-core projections (FROZEN). 160 blocks x 512 threads.
// ---------------------------------------------------------------------------
#define SA 264
#define SB 136
#define SC 136
#define SMEM_PROJ ((64 * SA + 256 * SB) * 2)

__global__ __launch_bounds__(512) void proj_mma_kernel(
    const float* __restrict__ queries, const float* __restrict__ keys,
    const float* __restrict__ Wq, const float* __restrict__ Wk)
{
    extern __shared__ __half smh[];
    __half* smA = smh;
    __half* smB = smh + 64 * SA;

    int tid = threadIdx.x;
    int rb = blockIdx.x * 64;
    bool isQ = rb < B_ * Q_;
    const float* src = isQ ? (queries + rb * D_) : (keys + (rb - B_ * Q_) * D_);
    const float* W   = isQ ? Wq : Wk;

    {
        float4 v[8];
        #pragma unroll
        for (int l = 0; l < 8; l++) v[l] = ((const float4*)src)[tid + 512 * l];
        #pragma unroll
        for (int l = 0; l < 8; l++) {
            int i = tid + 512 * l;
            int r = i >> 6, c4 = i & 63;
            *(__half2*)&smA[r * SA + c4 * 4]     = __floats2half2_rn(v[l].x, v[l].y);
            *(__half2*)&smA[r * SA + c4 * 4 + 2] = __floats2half2_rn(v[l].z, v[l].w);
        }
    }
    #pragma unroll
    for (int g = 0; g < 2; g++) {
        float4 v[8];
        #pragma unroll
        for (int l = 0; l < 8; l++)
            v[l] = ((const float4*)W)[tid + 512 * (g * 8 + l)];
        #pragma unroll
        for (int l = 0; l < 8; l++) {
            int i = tid + 512 * (g * 8 + l);
            int r = i >> 5, c4 = i & 31;
            *(__half2*)&smB[r * SB + c4 * 4]     = __floats2half2_rn(v[l].x, v[l].y);
            *(__half2*)&smB[r * SB + c4 * 4 + 2] = __floats2half2_rn(v[l].z, v[l].w);
        }
    }
    __syncthreads();

    int wid = tid >> 5, lane = tid & 31;
    int wm = (wid >> 2) * 16;
    int wn = (wid & 3) * 32;

    float acc[4][4];
    #pragma unroll
    for (int t = 0; t < 4; t++) {
        #pragma unroll
        for (int u = 0; u < 4; u++) acc[t][u] = 0.f;
    }

    unsigned int aBase = smem_u32(smA) +
        ((wm + (lane & 15)) * SA + (lane >> 4) * 8) * 2;
    unsigned int bBase = smem_u32(smB) +
        ((lane & 15) * SB + wn + (lane >> 4) * 8) * 2;

    #pragma unroll
    for (int k = 0; k < 16; k++) {
        unsigned int a0, a1, a2, a3;
        ldsm_x4(a0, a1, a2, a3, aBase + k * 32);
        #pragma unroll
        for (int nt = 0; nt < 2; nt++) {
            unsigned int b0, b1, b2, b3;
            ldsm_x4t(b0, b1, b2, b3, bBase + (k * 16 * SB + nt * 16) * 2);
            mma16816(acc[nt * 2],     a0, a1, a2, a3, b0, b1);
            mma16816(acc[nt * 2 + 1], a0, a1, a2, a3, b2, b3);
        }
    }
    __syncthreads();

    __half* smC = smA;
    #pragma unroll
    for (int t = 0; t < 4; t++) {
        int col = wn + t * 8 + 2 * (lane & 3);
        int r0  = wm + (lane >> 2);
        *(__half2*)&smC[r0 * SC + col]       = __floats2half2_rn(acc[t][0], acc[t][1]);
        *(__half2*)&smC[(r0 + 8) * SC + col] = __floats2half2_rn(acc[t][2], acc[t][3]);
    }
    __syncthreads();

    if (isQ) {
        #pragma unroll
        for (int l = 0; l < 16; l++) {
            int i = tid + 512 * l;
            int r = i >> 7, h = i & 127;
            __half v = smC[r * SC + h];
            g_q2[(rb + r) * H_ + h] = __halves2half2(v, v);
        }
    } else {
        int rk0 = rb - B_ * Q_;
        int b = rk0 >> 10, kt = (rk0 & 1023) >> 7, slot = (rk0 >> 6) & 1;
        __half* base = (__half*)g_k2 + (b * 8 + kt) * 64 * H_ * 2 + slot;
        #pragma unroll
        for (int l = 0; l < 16; l++) {
            int i = tid + 512 * l;
            int r = i >> 7, h = i & 127;
            base[(r * H_ + h) * 2] = smC[r * SC + h];
        }
    }
}

// ---------------------------------------------------------------------------
// Kernel 2: scores only (FROZEN). grid (Q/8, K/128, B), 256 threads.
// ---------------------------------------------------------------------------
__global__ __launch_bounds__(256) void scores_kernel(const float* __restrict__ w_v)
{
    __shared__ float ksw[64 * RPAD];
    __shared__ float qsw[8 * RPAD];
    __shared__ float wvs[RPAD];

    int b  = blockIdx.z;
    int kt = blockIdx.y;
    int q0 = blockIdx.x * 8;
    int tid = threadIdx.x;

    const float4* srck = (const float4*)(g_k2 + (b * 8 + kt) * 64 * H_);
    #pragma unroll
    for (int l = 0; l < 8; l++) {
        int i = tid + 256 * l;
        int r = i >> 5, c = i & 31;
        *(float4*)(ksw + r * RPAD + c * 4) = srck[i];
    }
    {
        int r = tid >> 5, c = tid & 31;
        *(float4*)(qsw + r * RPAD + c * 4) =
            ((const float4*)(g_q2 + (b * Q_ + q0 + r) * H_))[c];
    }
    if (tid < 128) {
        __half v = __float2half(w_v[tid]);
        ((__half2*)wvs)[tid] = __halves2half2(v, v);
    }
    __syncthreads();

    int qg = tid >> 6;
    int j  = tid & 63;
    const float4* qa4 = (const float4*)(qsw + (qg * 2    ) * RPAD);
    const float4* qb4 = (const float4*)(qsw + (qg * 2 + 1) * RPAD);
    const float4* kp4 = (const float4*)(ksw + j * RPAD);
    const float4* wv4 = (const float4*)wvs;

    float S00 = 0.f, S01 = 0.f, S10 = 0.f, S11 = 0.f;
    #pragma unroll 4
    for (int hh = 0; hh < 16; hh++) {
        __half2 sa = __float2half2_rn(0.f);
        __half2 sb = __float2half2_rn(0.f);
        #pragma unroll
        for (int t = 0; t < 2; t++) {
            int h4 = hh * 2 + t;
            float4 kv = kp4[h4];
            float4 qa = qa4[h4];
            float4 qb = qb4[h4];
            float4 wf = wv4[h4];
            const __half2* kh  = (const __half2*)&kv;
            const __half2* qah = (const __half2*)&qa;
            const __half2* qbh = (const __half2*)&qb;
            const __half2* wh  = (const __half2*)&wf;
            #pragma unroll
            for (int u = 0; u < 4; u++) {
                __half2 ta = tanh_h2(__hadd2(qah[u], kh[u]));
                __half2 tb = tanh_h2(__hadd2(qbh[u], kh[u]));
                sa = __hfma2(wh[u], ta, sa);
                sb = __hfma2(wh[u], tb, sb);
            }
        }
        float2 fa = __half22float2(sa);
        float2 fb = __half22float2(sb);
        S00 += fa.x; S01 += fa.y;
        S10 += fb.x; S11 += fb.y;
    }

    float* dst = g_sc + (b * Q_ + q0 + qg * 2) * K_ + kt * 128;
    dst[j]           = S00;
    dst[j + 64]      = S01;
    dst[K_ + j]      = S10;
    dst[K_ + j + 64] = S11;
}

// ---------------------------------------------------------------------------
// Kernel 3 v3: masked softmax + tensor-core AV.
// grid (Q/16, B) = 128 CTAs, 512 threads (16 warps).
// Softmax: warp w = q-row w, probs stored fp16 in smem.
// AV: P[16x1024]h x V[1024x128]h via mma.sync, V staged in 8 chunks of 128k.
// ---------------------------------------------------------------------------
#define SP 1032           // P smem stride in halfs (1024 + 8)
#define SV 136            // V chunk stride in halfs (128 + 8)
#define SMEM_AV ((16 * SP + 128 * SV) * 2)

__global__ __launch_bounds__(512) void smax_av_mma_kernel(
    const float* __restrict__ values, const int* __restrict__ valid_lens,
    float* __restrict__ out)
{
    extern __shared__ __half sm2[];
    __half* smP = sm2;                 // 16 x SP
    __half* smV = sm2 + 16 * SP;       // 128 x SV

    int b  = blockIdx.y;
    int q0 = blockIdx.x * 16;
    int tid = threadIdx.x;
    int wid = tid >> 5, lane = tid & 31;
    int vlen = valid_lens[b];

    // ---- masked softmax: warp w handles q-row w; write probs fp16 ----
    {
        const float* row = g_sc + (b * Q_ + q0 + wid) * K_;
        float v[32];
        float m = -3e38f;
        #pragma unroll
        for (int jj = 0; jj < 32; jj++) {
            int k = lane + 32 * jj;
            float s = (k < vlen) ? row[k] : -1e6f;
            v[jj] = s;
            m = fmaxf(m, s);
        }
        #pragma unroll
        for (int off = 16; off; off >>= 1)
            m = fmaxf(m, __shfl_xor_sync(0xffffffffu, m, off));
        float sum = 0.f;
        #pragma unroll
        for (int jj = 0; jj < 32; jj++) { v[jj] = __expf(v[jj] - m); sum += v[jj]; }
        #pragma unroll
        for (int off = 16; off; off >>= 1)
            sum += __shfl_xor_sync(0xffffffffu, sum, off);
        float inv = 1.f / sum;
        #pragma unroll
        for (int jj = 0; jj < 32; jj++)
            smP[wid * SP + lane + 32 * jj] = __float2half(v[jj] * inv);
    }
    __syncthreads();

    float acc[2][4];
    #pragma unroll
    for (int t = 0; t < 2; t++) {
        #pragma unroll
        for (int u = 0; u < 4; u++) acc[t][u] = 0.f;
    }

    unsigned int aBase = smem_u32(smP) +
        ((lane & 15) * SP + (lane >> 4) * 8) * 2;
    unsigned int bBase = smem_u32(smV) +
        ((lane & 15) * SV + wid * 16 + (lane >> 4) * 8) * 2;

    const float4* vb = (const float4*)(values + b * K_ * DV_);

    for (int c = 0; c < 8; c++) {
        // stage V chunk: 128 k-rows x 128 dv fp32 -> fp16 (4096 float4, 8/thr)
        float4 vv[8];
        #pragma unroll
        for (int l = 0; l < 8; l++) vv[l] = vb[c * 4096 + tid + 512 * l];
        #pragma unroll
        for (int l = 0; l < 8; l++) {
            int i = tid + 512 * l;
            int r = i >> 5, c4 = i & 31;
            *(__half2*)&smV[r * SV + c4 * 4]     = __floats2half2_rn(vv[l].x, vv[l].y);
            *(__half2*)&smV[r * SV + c4 * 4 + 2] = __floats2half2_rn(vv[l].z, vv[l].w);
        }
        __syncthreads();

        if (wid < 8) {
            #pragma unroll
            for (int s = 0; s < 8; s++) {
                unsigned int a0, a1, a2, a3;
                ldsm_x4(a0, a1, a2, a3, aBase + (c * 128 + s * 16) * 2);
                unsigned int b0, b1, b2, b3;
                ldsm_x4t(b0, b1, b2, b3, bBase + (s * 16 * SV) * 2);
                mma16816(acc[0], a0, a1, a2, a3, b0, b1);
                mma16816(acc[1], a0, a1, a2, a3, b2, b3);
            }
        }
        __syncthreads();
    }

    if (wid < 8) {
        #pragma unroll
        for (int t = 0; t < 2; t++) {
            int col = wid * 16 + t * 8 + 2 * (lane & 3);
            int r0  = lane >> 2;
            *(float2*)&out[(b * Q_ + q0 + r0) * DV_ + col] =
                make_float2(acc[t][0], acc[t][1]);
            *(float2*)&out[(b * Q_ + q0 + r0 + 8) * DV_ + col] =
                make_float2(acc[t][2], acc[t][3]);
        }
    }
}

extern "C" void kernel_launch(void* const* d_in, const int* in_sizes, int n_in,
                              void* d_out, int out_size)
{
    const float* queries    = (const float*)d_in[0];
    const float* keys       = (const float*)d_in[1];
    const float* values     = (const float*)d_in[2];
    const int*   valid_lens = (const int*)  d_in[3];
    const float* W_q        = (const float*)d_in[4];
    const float* W_k        = (const float*)d_in[5];
    const float* w_v        = (const float*)d_in[6];
    float* out = (float*)d_out;

    cudaFuncSetAttribute(proj_mma_kernel,
                         cudaFuncAttributeMaxDynamicSharedMemorySize, SMEM_PROJ);
    cudaFuncSetAttribute(smax_av_mma_kernel,
                         cudaFuncAttributeMaxDynamicSharedMemorySize, SMEM_AV);

    proj_mma_kernel<<<(B_ * Q_ + B_ * K_) / 64, 512, SMEM_PROJ>>>(
        queries, keys, W_q, W_k);
    scores_kernel<<<dim3(Q_ / 8, K_ / 128, B_), 256>>>(w_v);
    smax_av_mma_kernel<<<dim3(Q_ / 16, B_), 512, SMEM_AV>>>(
        values, valid_lens, out);
}